// round 9
// baseline (speedup 1.0000x reference)
#include <cuda_runtime.h>
#include <cuda_bf16.h>
#include <cstdint>

#define NN 100000
#define HALF_N 50000
#define EE 1600000
#define FD 128
#define BB 50
#define PP 2000
#define CC 10
#define KINV (1.0f/30.0f)
#define NBLK ((NN + 255) / 256)   // 391

// Scratch (static device globals — no allocation at launch time).
static __device__ uint32_t g_tmpb[NN*64];    // (A@W) as packed bf16x2 (UNSCALED)
static __device__ float    g_h1[NN*FD];      // relu(layer-1 output)
static __device__ float    g_h2[NN*FD];      // relu(layer-2 output)
static __device__ float    g_inv[NN];        // rsqrt(deg+1)
static __device__ float    g_part[BB*8*FD];  // pooling partials
static __device__ int      g_cnt[NN];
static __device__ int      g_cur[NN];
static __device__ int      g_off[NN];
static __device__ int      g_src[EE];
static __device__ int      g_blksum[NBLK];
static __device__ int      g_blkoff[NBLK];

// bf16x2 helpers
__device__ __forceinline__ float bf_lo(uint32_t u) { return __uint_as_float(u << 16); }
__device__ __forceinline__ float bf_hi(uint32_t u) { return __uint_as_float(u & 0xffff0000u); }
__device__ __forceinline__ uint32_t bf_pack(float a, float b) {
    __nv_bfloat162 h = __float22bfloat162_rn(make_float2(a, b));
    return *reinterpret_cast<uint32_t*>(&h);
}

// ---------------- CSR-by-dst construction ----------------

__global__ void k_zero() {
    int i = blockIdx.x*blockDim.x + threadIdx.x;
    if (i < NN) { g_cnt[i] = 0; g_cur[i] = 0; }
}

__global__ void k_hist(const int* __restrict__ ei, int E) {
    int e = blockIdx.x*blockDim.x + threadIdx.x;
    if (e < E) atomicAdd(&g_cnt[ei[E + e]], 1);
}

__global__ void k_scan_block() {
    __shared__ int sh[256];
    int t = threadIdx.x;
    int i = blockIdx.x*256 + t;
    int v = (i < NN) ? g_cnt[i] : 0;
    sh[t] = v;
    __syncthreads();
    #pragma unroll
    for (int d = 1; d < 256; d <<= 1) {
        int x = (t >= d) ? sh[t-d] : 0;
        __syncthreads();
        sh[t] += x;
        __syncthreads();
    }
    if (i < NN) {
        g_off[i] = sh[t] - v;
        g_inv[i] = rsqrtf((float)v + 1.0f);
    }
    if (t == 255) g_blksum[blockIdx.x] = sh[255];
}

__global__ void k_scan_top() {
    __shared__ int sh[512];
    int t = threadIdx.x;
    int v = (t < NBLK) ? g_blksum[t] : 0;
    sh[t] = v;
    __syncthreads();
    #pragma unroll
    for (int d = 1; d < 512; d <<= 1) {
        int x = (t >= d) ? sh[t-d] : 0;
        __syncthreads();
        sh[t] += x;
        __syncthreads();
    }
    if (t < NBLK) g_blkoff[t] = sh[t] - v;
}

__global__ void k_scan_add() {
    int i = blockIdx.x*256 + threadIdx.x;
    if (i < NN) g_off[i] += g_blkoff[blockIdx.x];
}

__global__ void k_fill(const int* __restrict__ ei, int E) {
    int e = blockIdx.x*blockDim.x + threadIdx.x;
    if (e < E) {
        int s = ei[e];
        int d = ei[E + e];
        int pos = g_off[d] + atomicAdd(&g_cur[d], 1);
        g_src[pos] = s;
    }
}

// ---------------- FFMA SGEMM (row-half): tmpb = bf16(A @ W) ----------------
// No inv scaling here (moved to gather) -> GEMM1 has no CSR dependency.

template<int LAYER>
__global__ void __launch_bounds__(256)
k_gemm(const float* __restrict__ X, const float* __restrict__ W,
       int row_base, int row_end) {
    const float* A = (LAYER == 1) ? X : (const float*)g_h1;

    __shared__ float As[32][129];   // transposed A chunk: As[kk][row]
    __shared__ float Ws[32][128];   // W chunk: Ws[kk][col]

    const int tid  = threadIdx.x;
    const int row0 = row_base + blockIdx.x * 128;
    const int rq   = tid >> 4;
    const int cq   = tid & 15;

    float acc[8][8];
    #pragma unroll
    for (int i = 0; i < 8; i++)
        #pragma unroll
        for (int j = 0; j < 8; j++) acc[i][j] = 0.f;

    for (int k0 = 0; k0 < FD; k0 += 32) {
        #pragma unroll
        for (int i = 0; i < 4; i++) {
            int s  = tid + i*256;
            int r  = s >> 3;
            int kv = s & 7;
            int grow = row0 + r;
            float4 v = make_float4(0.f, 0.f, 0.f, 0.f);
            if (grow < row_end)
                v = *reinterpret_cast<const float4*>(A + (size_t)grow*FD + k0 + kv*4);
            As[kv*4+0][r] = v.x; As[kv*4+1][r] = v.y;
            As[kv*4+2][r] = v.z; As[kv*4+3][r] = v.w;
        }
        #pragma unroll
        for (int i = 0; i < 4; i++) {
            int s  = tid + i*256;
            int kk = s >> 5;
            int jv = s & 31;
            *reinterpret_cast<float4*>(&Ws[kk][jv*4]) =
                *reinterpret_cast<const float4*>(W + (size_t)(k0+kk)*FD + jv*4);
        }
        __syncthreads();

        #pragma unroll
        for (int kk = 0; kk < 32; kk++) {
            float a[8], w[8];
            #pragma unroll
            for (int i = 0; i < 8; i++) a[i] = As[kk][rq*8 + i];
            *reinterpret_cast<float4*>(&w[0]) =
                *reinterpret_cast<const float4*>(&Ws[kk][cq*8]);
            *reinterpret_cast<float4*>(&w[4]) =
                *reinterpret_cast<const float4*>(&Ws[kk][cq*8 + 4]);
            #pragma unroll
            for (int i = 0; i < 8; i++)
                #pragma unroll
                for (int j = 0; j < 8; j++)
                    acc[i][j] = fmaf(a[i], w[j], acc[i][j]);
        }
        __syncthreads();
    }

    // Epilogue: pack acc into bf16x2 (unscaled)
    #pragma unroll
    for (int i = 0; i < 8; i++) {
        int grow = row0 + rq*8 + i;
        if (grow < row_end) {
            uint4 o;
            o.x = bf_pack(acc[i][0], acc[i][1]);
            o.y = bf_pack(acc[i][2], acc[i][3]);
            o.z = bf_pack(acc[i][4], acc[i][5]);
            o.w = bf_pack(acc[i][6], acc[i][7]);
            *reinterpret_cast<uint4*>(g_tmpb + (size_t)grow*64 + cq*4) = o;
        }
    }
}

// ---------------- CSR gather (row-half, bf16 payload): one warp per dst ----------------
// H[dst] = relu( inv[dst] * ( inv[dst]*tmp[dst] + sum_src inv[src]*tmp[src] ) + b )

template<int LAYER>
__global__ void __launch_bounds__(256)
k_gather(const float* __restrict__ bias, int node_base, int node_end) {
    int node = node_base + blockIdx.x*8 + (threadIdx.x >> 5);
    if (node >= node_end) return;
    float* H = (LAYER == 1) ? g_h1 : g_h2;

    const int lane  = threadIdx.x & 31;
    const int start = g_off[node];
    const int deg   = g_cnt[node];
    const float invd = g_inv[node];

    // self term: inv[d]*tmp[d]
    uint2 sv = *reinterpret_cast<const uint2*>(g_tmpb + (size_t)node*64 + lane*2);
    float4 acc0 = make_float4(bf_lo(sv.x)*invd, bf_hi(sv.x)*invd,
                              bf_lo(sv.y)*invd, bf_hi(sv.y)*invd);
    float4 acc1 = make_float4(0.f, 0.f, 0.f, 0.f);

    for (int base = 0; base < deg; base += 32) {
        int n = deg - base; if (n > 32) n = 32;
        int s = 0; float ci = 0.f;
        if (base + lane < deg) {
            s  = g_src[start + base + lane];
            ci = g_inv[s];
        }
        int j = 0;
        for (; j + 1 < n; j += 2) {
            int   s0 = __shfl_sync(0xffffffff, s,  j);
            float c0 = __shfl_sync(0xffffffff, ci, j);
            int   s1 = __shfl_sync(0xffffffff, s,  j+1);
            float c1 = __shfl_sync(0xffffffff, ci, j+1);
            uint2 v0 = *reinterpret_cast<const uint2*>(g_tmpb + (size_t)s0*64 + lane*2);
            uint2 v1 = *reinterpret_cast<const uint2*>(g_tmpb + (size_t)s1*64 + lane*2);
            acc0.x = fmaf(bf_lo(v0.x), c0, acc0.x);
            acc0.y = fmaf(bf_hi(v0.x), c0, acc0.y);
            acc0.z = fmaf(bf_lo(v0.y), c0, acc0.z);
            acc0.w = fmaf(bf_hi(v0.y), c0, acc0.w);
            acc1.x = fmaf(bf_lo(v1.x), c1, acc1.x);
            acc1.y = fmaf(bf_hi(v1.x), c1, acc1.y);
            acc1.z = fmaf(bf_lo(v1.y), c1, acc1.z);
            acc1.w = fmaf(bf_hi(v1.y), c1, acc1.w);
        }
        if (j < n) {
            int   s0 = __shfl_sync(0xffffffff, s,  j);
            float c0 = __shfl_sync(0xffffffff, ci, j);
            uint2 v0 = *reinterpret_cast<const uint2*>(g_tmpb + (size_t)s0*64 + lane*2);
            acc0.x = fmaf(bf_lo(v0.x), c0, acc0.x);
            acc0.y = fmaf(bf_hi(v0.x), c0, acc0.y);
            acc0.z = fmaf(bf_lo(v0.y), c0, acc0.z);
            acc0.w = fmaf(bf_hi(v0.y), c0, acc0.w);
        }
    }

    float4 b4 = *reinterpret_cast<const float4*>(bias + lane*4);
    float4 h;
    h.x = fmaxf(fmaf(acc0.x + acc1.x, invd, b4.x), 0.f);
    h.y = fmaxf(fmaf(acc0.y + acc1.y, invd, b4.y), 0.f);
    h.z = fmaxf(fmaf(acc0.z + acc1.z, invd, b4.z), 0.f);
    h.w = fmaxf(fmaf(acc0.w + acc1.w, invd, b4.w), 0.f);
    *reinterpret_cast<float4*>(H + (size_t)node*FD + lane*4) = h;
}

// ---------------- pooling + final ----------------

__global__ void k_pool() {
    int b = blockIdx.x >> 3;
    int q = blockIdx.x & 7;
    int d = threadIdx.x;
    const float* base = g_h2 + ((size_t)(b*PP + q*(PP/8)))*FD + d;
    float s = 0.f;
    #pragma unroll 4
    for (int n = 0; n < PP/8; n++) s += base[(size_t)n*FD];
    g_part[blockIdx.x*FD + d] = s;
}

__global__ void k_final(const float* __restrict__ Wl, const float* __restrict__ bl,
                        float* __restrict__ out) {
    int t = threadIdx.x;
    if (t >= BB*CC) return;
    int b = t / CC, c = t % CC;
    float s = 0.f;
    for (int d = 0; d < FD; d++) {
        float p = 0.f;
        #pragma unroll
        for (int q = 0; q < 8; q++) p += g_part[(b*8 + q)*FD + d];
        s = fmaf(p, Wl[d*CC + c], s);
    }
    out[t] = fmaf(s, KINV, bl[c]);
}

// ---------------- launch: two-stream pipelined graph ----------------

extern "C" void kernel_launch(void* const* d_in, const int* in_sizes, int n_in,
                              void* d_out, int out_size) {
    const float* x  = (const float*)d_in[0];
    const int*   ei = (const int*)  d_in[1];
    const float* W1 = (const float*)d_in[3];
    const float* b1 = (const float*)d_in[4];
    const float* W2 = (const float*)d_in[5];
    const float* b2 = (const float*)d_in[6];
    // d_in[7]=Wa, d_in[8]=ba dead (softmax rows sum to 1); d_in[2]=batch implied
    const float* Wl = (const float*)d_in[9];
    const float* bl = (const float*)d_in[10];
    float* out = (float*)d_out;

    const int E = in_sizes[1] / 2;

    // Host-side resources (no device memory). Created once.
    static cudaStream_t sb = nullptr;
    static cudaEvent_t eFork, eG1a, eG1b, eg1a, eg1b, eG2a, eG2b, eJoin;
    if (!sb) {
        cudaStreamCreateWithFlags(&sb, cudaStreamNonBlocking);
        cudaEventCreateWithFlags(&eFork, cudaEventDisableTiming);
        cudaEventCreateWithFlags(&eG1a,  cudaEventDisableTiming);
        cudaEventCreateWithFlags(&eG1b,  cudaEventDisableTiming);
        cudaEventCreateWithFlags(&eg1a,  cudaEventDisableTiming);
        cudaEventCreateWithFlags(&eg1b,  cudaEventDisableTiming);
        cudaEventCreateWithFlags(&eG2a,  cudaEventDisableTiming);
        cudaEventCreateWithFlags(&eG2b,  cudaEventDisableTiming);
        cudaEventCreateWithFlags(&eJoin, cudaEventDisableTiming);
    }

    const int gemm_half_grid   = (HALF_N + 127)/128;   // 391
    const int gather_half_grid = (HALF_N + 7)/8;       // 6250

    // Fork: stream sb joins the capture
    cudaEventRecord(eFork, 0);
    cudaStreamWaitEvent(sb, eFork, 0);

    // Stream sb: CSR build (independent of GEMM1)
    k_zero      <<<NBLK, 256, 0, sb>>>();
    k_hist      <<<(E + 511)/512, 512, 0, sb>>>(ei, E);
    k_scan_block<<<NBLK, 256, 0, sb>>>();
    k_scan_top  <<<1, 512, 0, sb>>>();
    k_scan_add  <<<NBLK, 256, 0, sb>>>();
    k_fill      <<<(E + 511)/512, 512, 0, sb>>>(ei, E);

    // Stream 0: GEMM1 halves (no CSR dependency: inv moved to gather)
    k_gemm<1><<<gemm_half_grid, 256>>>(x, W1, 0, HALF_N);
    cudaEventRecord(eG1a, 0);
    k_gemm<1><<<gemm_half_grid, 256>>>(x, W1, HALF_N, NN);
    cudaEventRecord(eG1b, 0);

    // Stream sb: gather1 halves (after CSR done on sb; wait GEMM halves)
    cudaStreamWaitEvent(sb, eG1a, 0);
    k_gather<1><<<gather_half_grid, 256, 0, sb>>>(b1, 0, HALF_N);
    cudaEventRecord(eg1a, sb);
    cudaStreamWaitEvent(sb, eG1b, 0);
    k_gather<1><<<gather_half_grid, 256, 0, sb>>>(b1, HALF_N, NN);
    cudaEventRecord(eg1b, sb);

    // Stream 0: GEMM2 halves (row i of h1 -> row i of tmp; half-wise dependency)
    cudaStreamWaitEvent(0, eg1a, 0);
    k_gemm<2><<<gemm_half_grid, 256>>>(x /*unused*/, W2, 0, HALF_N);
    cudaEventRecord(eG2a, 0);
    cudaStreamWaitEvent(0, eg1b, 0);
    k_gemm<2><<<gemm_half_grid, 256>>>(x /*unused*/, W2, HALF_N, NN);
    cudaEventRecord(eG2b, 0);

    // Stream sb: gather2 halves, then pool + final
    cudaStreamWaitEvent(sb, eG2a, 0);
    k_gather<2><<<gather_half_grid, 256, 0, sb>>>(b2, 0, HALF_N);
    cudaStreamWaitEvent(sb, eG2b, 0);
    k_gather<2><<<gather_half_grid, 256, 0, sb>>>(b2, HALF_N, NN);
    k_pool <<<BB*8, FD, 0, sb>>>();
    k_final<<<1, 512, 0, sb>>>(Wl, bl, out);

    // Join back to stream 0
    cudaEventRecord(eJoin, sb);
    cudaStreamWaitEvent(0, eJoin, 0);
}

// round 10
// speedup vs baseline: 1.2454x; 1.2454x over previous
#include <cuda_runtime.h>
#include <cuda_bf16.h>
#include <cstdint>

#define NN 100000
#define EE 1600000
#define FD 128
#define BB 50
#define PP 2000
#define CC 10
#define KINV (1.0f/30.0f)
#define NBLK ((NN + 255) / 256)   // 391

// Scratch (static device globals — no allocation at launch time).
static __device__ uint32_t g_tmpb[NN*64];    // (A@W) as packed bf16x2 (UNSCALED)
static __device__ float    g_h1[NN*FD];      // relu(layer-1 output)
static __device__ float    g_inv[NN];        // rsqrt(deg+1)
static __device__ float    g_part[BB*FD];    // fused pooling accumulators
static __device__ int      g_cnt[NN];
static __device__ int      g_cur[NN];
static __device__ int      g_off[NN];
static __device__ int      g_src[EE];
static __device__ int      g_blksum[NBLK];
static __device__ int      g_blkoff[NBLK];

// bf16x2 helpers
__device__ __forceinline__ float bf_lo(uint32_t u) { return __uint_as_float(u << 16); }
__device__ __forceinline__ float bf_hi(uint32_t u) { return __uint_as_float(u & 0xffff0000u); }
__device__ __forceinline__ uint32_t bf_pack(float a, float b) {
    __nv_bfloat162 h = __float22bfloat162_rn(make_float2(a, b));
    return *reinterpret_cast<uint32_t*>(&h);
}

// ---------------- CSR-by-dst construction ----------------

__global__ void k_zero() {
    int i = blockIdx.x*blockDim.x + threadIdx.x;
    if (i < NN) { g_cnt[i] = 0; g_cur[i] = 0; }
    if (i < BB*FD) g_part[i] = 0.f;
}

__global__ void k_hist(const int* __restrict__ ei, int E) {
    int e = blockIdx.x*blockDim.x + threadIdx.x;
    if (e < E) atomicAdd(&g_cnt[ei[E + e]], 1);
}

__global__ void k_scan_block() {
    __shared__ int sh[256];
    int t = threadIdx.x;
    int i = blockIdx.x*256 + t;
    int v = (i < NN) ? g_cnt[i] : 0;
    sh[t] = v;
    __syncthreads();
    #pragma unroll
    for (int d = 1; d < 256; d <<= 1) {
        int x = (t >= d) ? sh[t-d] : 0;
        __syncthreads();
        sh[t] += x;
        __syncthreads();
    }
    if (i < NN) {
        g_off[i] = sh[t] - v;
        g_inv[i] = rsqrtf((float)v + 1.0f);
    }
    if (t == 255) g_blksum[blockIdx.x] = sh[255];
}

__global__ void k_scan_top() {
    __shared__ int sh[512];
    int t = threadIdx.x;
    int v = (t < NBLK) ? g_blksum[t] : 0;
    sh[t] = v;
    __syncthreads();
    #pragma unroll
    for (int d = 1; d < 512; d <<= 1) {
        int x = (t >= d) ? sh[t-d] : 0;
        __syncthreads();
        sh[t] += x;
        __syncthreads();
    }
    if (t < NBLK) g_blkoff[t] = sh[t] - v;
}

__global__ void k_scan_add() {
    int i = blockIdx.x*256 + threadIdx.x;
    if (i < NN) g_off[i] += g_blkoff[blockIdx.x];
}

__global__ void k_fill(const int* __restrict__ ei, int E) {
    int e = blockIdx.x*blockDim.x + threadIdx.x;
    if (e < E) {
        int s = ei[e];
        int d = ei[E + e];
        int pos = g_off[d] + atomicAdd(&g_cur[d], 1);
        g_src[pos] = s;
    }
}

// ---------------- FFMA SGEMM: tmpb = bf16(A @ W) (unscaled) ----------------

template<int LAYER>
__global__ void __launch_bounds__(256)
k_gemm(const float* __restrict__ X, const float* __restrict__ W) {
    const float* A = (LAYER == 1) ? X : (const float*)g_h1;

    __shared__ float As[32][129];   // transposed A chunk: As[kk][row]
    __shared__ float Ws[32][128];   // W chunk: Ws[kk][col]

    const int tid  = threadIdx.x;
    const int row0 = blockIdx.x * 128;
    const int rq   = tid >> 4;
    const int cq   = tid & 15;

    float acc[8][8];
    #pragma unroll
    for (int i = 0; i < 8; i++)
        #pragma unroll
        for (int j = 0; j < 8; j++) acc[i][j] = 0.f;

    for (int k0 = 0; k0 < FD; k0 += 32) {
        #pragma unroll
        for (int i = 0; i < 4; i++) {
            int s  = tid + i*256;
            int r  = s >> 3;
            int kv = s & 7;
            int grow = row0 + r;
            float4 v = make_float4(0.f, 0.f, 0.f, 0.f);
            if (grow < NN)
                v = *reinterpret_cast<const float4*>(A + (size_t)grow*FD + k0 + kv*4);
            As[kv*4+0][r] = v.x; As[kv*4+1][r] = v.y;
            As[kv*4+2][r] = v.z; As[kv*4+3][r] = v.w;
        }
        #pragma unroll
        for (int i = 0; i < 4; i++) {
            int s  = tid + i*256;
            int kk = s >> 5;
            int jv = s & 31;
            *reinterpret_cast<float4*>(&Ws[kk][jv*4]) =
                *reinterpret_cast<const float4*>(W + (size_t)(k0+kk)*FD + jv*4);
        }
        __syncthreads();

        #pragma unroll
        for (int kk = 0; kk < 32; kk++) {
            float a[8], w[8];
            #pragma unroll
            for (int i = 0; i < 8; i++) a[i] = As[kk][rq*8 + i];
            *reinterpret_cast<float4*>(&w[0]) =
                *reinterpret_cast<const float4*>(&Ws[kk][cq*8]);
            *reinterpret_cast<float4*>(&w[4]) =
                *reinterpret_cast<const float4*>(&Ws[kk][cq*8 + 4]);
            #pragma unroll
            for (int i = 0; i < 8; i++)
                #pragma unroll
                for (int j = 0; j < 8; j++)
                    acc[i][j] = fmaf(a[i], w[j], acc[i][j]);
        }
        __syncthreads();
    }

    #pragma unroll
    for (int i = 0; i < 8; i++) {
        int grow = row0 + rq*8 + i;
        if (grow < NN) {
            uint4 o;
            o.x = bf_pack(acc[i][0], acc[i][1]);
            o.y = bf_pack(acc[i][2], acc[i][3]);
            o.z = bf_pack(acc[i][4], acc[i][5]);
            o.w = bf_pack(acc[i][6], acc[i][7]);
            *reinterpret_cast<uint4*>(g_tmpb + (size_t)grow*64 + cq*4) = o;
        }
    }
}

// ---------------- gather core: h(node) as float4 per lane ----------------
// h = relu( inv[d] * ( inv[d]*tmp[d] + sum_src inv[s]*tmp[s] ) + bias )

__device__ __forceinline__ float4 gather_node(int node, int lane,
                                              const float* __restrict__ bias) {
    const int start = g_off[node];
    const int deg   = g_cnt[node];
    const float invd = g_inv[node];

    uint2 sv = *reinterpret_cast<const uint2*>(g_tmpb + (size_t)node*64 + lane*2);
    float4 acc0 = make_float4(bf_lo(sv.x)*invd, bf_hi(sv.x)*invd,
                              bf_lo(sv.y)*invd, bf_hi(sv.y)*invd);
    float4 acc1 = make_float4(0.f, 0.f, 0.f, 0.f);

    for (int base = 0; base < deg; base += 32) {
        int n = deg - base; if (n > 32) n = 32;
        int s = 0; float ci = 0.f;
        if (base + lane < deg) {
            s  = g_src[start + base + lane];
            ci = g_inv[s];
        }
        int j = 0;
        for (; j + 1 < n; j += 2) {
            int   s0 = __shfl_sync(0xffffffff, s,  j);
            float c0 = __shfl_sync(0xffffffff, ci, j);
            int   s1 = __shfl_sync(0xffffffff, s,  j+1);
            float c1 = __shfl_sync(0xffffffff, ci, j+1);
            uint2 v0 = *reinterpret_cast<const uint2*>(g_tmpb + (size_t)s0*64 + lane*2);
            uint2 v1 = *reinterpret_cast<const uint2*>(g_tmpb + (size_t)s1*64 + lane*2);
            acc0.x = fmaf(bf_lo(v0.x), c0, acc0.x);
            acc0.y = fmaf(bf_hi(v0.x), c0, acc0.y);
            acc0.z = fmaf(bf_lo(v0.y), c0, acc0.z);
            acc0.w = fmaf(bf_hi(v0.y), c0, acc0.w);
            acc1.x = fmaf(bf_lo(v1.x), c1, acc1.x);
            acc1.y = fmaf(bf_hi(v1.x), c1, acc1.y);
            acc1.z = fmaf(bf_lo(v1.y), c1, acc1.z);
            acc1.w = fmaf(bf_hi(v1.y), c1, acc1.w);
        }
        if (j < n) {
            int   s0 = __shfl_sync(0xffffffff, s,  j);
            float c0 = __shfl_sync(0xffffffff, ci, j);
            uint2 v0 = *reinterpret_cast<const uint2*>(g_tmpb + (size_t)s0*64 + lane*2);
            acc0.x = fmaf(bf_lo(v0.x), c0, acc0.x);
            acc0.y = fmaf(bf_hi(v0.x), c0, acc0.y);
            acc0.z = fmaf(bf_lo(v0.y), c0, acc0.z);
            acc0.w = fmaf(bf_hi(v0.y), c0, acc0.w);
        }
    }

    float4 b4 = *reinterpret_cast<const float4*>(bias + lane*4);
    float4 h;
    h.x = fmaxf(fmaf(acc0.x + acc1.x, invd, b4.x), 0.f);
    h.y = fmaxf(fmaf(acc0.y + acc1.y, invd, b4.y), 0.f);
    h.z = fmaxf(fmaf(acc0.z + acc1.z, invd, b4.z), 0.f);
    h.w = fmaxf(fmaf(acc0.w + acc1.w, invd, b4.w), 0.f);
    return h;
}

// Layer 1: write h1 rows (consumed by GEMM2)
__global__ void __launch_bounds__(256)
k_gather1(const float* __restrict__ bias) {
    int node = blockIdx.x*8 + (threadIdx.x >> 5);
    int lane = threadIdx.x & 31;
    float4 h = gather_node(node, lane, bias);
    *reinterpret_cast<float4*>(g_h1 + (size_t)node*FD + lane*4) = h;
}

// Layer 2 fused with pooling: block = 8 nodes of ONE graph (2000 % 8 == 0);
// reduce relu(h2) rows in smem, one atomicAdd per dim into g_part[graph].
__global__ void __launch_bounds__(256)
k_gather2_pool(const float* __restrict__ bias) {
    __shared__ float red[8][FD];
    int wid  = threadIdx.x >> 5;
    int lane = threadIdx.x & 31;
    int node = blockIdx.x*8 + wid;
    int b    = node / PP;                 // same for all 8 warps in the block

    float4 h = gather_node(node, lane, bias);
    *reinterpret_cast<float4*>(&red[wid][lane*4]) = h;
    __syncthreads();

    int t = threadIdx.x;
    if (t < FD) {
        float s = 0.f;
        #pragma unroll
        for (int w = 0; w < 8; w++) s += red[w][t];
        atomicAdd(&g_part[b*FD + t], s);
    }
}

// ---------------- final ----------------

__global__ void k_final(const float* __restrict__ Wl, const float* __restrict__ bl,
                        float* __restrict__ out) {
    int t = threadIdx.x;
    if (t >= BB*CC) return;
    int b = t / CC, c = t % CC;
    float s = 0.f;
    for (int d = 0; d < FD; d++)
        s = fmaf(g_part[b*FD + d], Wl[d*CC + c], s);
    out[t] = fmaf(s, KINV, bl[c]);
}

// ---------------- launch: CSR build overlapped with GEMM1, rest serial ----------------

extern "C" void kernel_launch(void* const* d_in, const int* in_sizes, int n_in,
                              void* d_out, int out_size) {
    const float* x  = (const float*)d_in[0];
    const int*   ei = (const int*)  d_in[1];
    const float* W1 = (const float*)d_in[3];
    const float* b1 = (const float*)d_in[4];
    const float* W2 = (const float*)d_in[5];
    const float* b2 = (const float*)d_in[6];
    // d_in[7]=Wa, d_in[8]=ba dead (softmax rows sum to 1); d_in[2]=batch implied
    const float* Wl = (const float*)d_in[9];
    const float* bl = (const float*)d_in[10];
    float* out = (float*)d_out;

    const int E = in_sizes[1] / 2;

    static cudaStream_t sb = nullptr;
    static cudaEvent_t eFork, eCSR;
    if (!sb) {
        cudaStreamCreateWithFlags(&sb, cudaStreamNonBlocking);
        cudaEventCreateWithFlags(&eFork, cudaEventDisableTiming);
        cudaEventCreateWithFlags(&eCSR,  cudaEventDisableTiming);
    }

    const int gemm_grid   = (NN + 127)/128;   // 782
    const int gather_grid = NN / 8;           // 12500

    // Side stream: CSR build (+ g_part zero), fully independent of GEMM1
    cudaEventRecord(eFork, 0);
    cudaStreamWaitEvent(sb, eFork, 0);
    k_zero      <<<NBLK, 256, 0, sb>>>();
    k_hist      <<<(E + 511)/512, 512, 0, sb>>>(ei, E);
    k_scan_block<<<NBLK, 256, 0, sb>>>();
    k_scan_top  <<<1, 512, 0, sb>>>();
    k_scan_add  <<<NBLK, 256, 0, sb>>>();
    k_fill      <<<(E + 511)/512, 512, 0, sb>>>(ei, E);
    cudaEventRecord(eCSR, sb);

    // Main stream: GEMM1 concurrent with CSR build
    k_gemm<1><<<gemm_grid, 256>>>(x, W1);
    cudaStreamWaitEvent(0, eCSR, 0);

    k_gather1<<<gather_grid, 256>>>(b1);
    k_gemm<2><<<gemm_grid, 256>>>(x /*unused*/, W2);
    k_gather2_pool<<<gather_grid, 256>>>(b2);
    k_final<<<1, 512>>>(Wl, bl, out);
}